// round 2
// baseline (speedup 1.0000x reference)
#include <cuda_runtime.h>
#include <cstdint>

#define NN 50000
#define EE 640000
#define FIN 768
#define HD 128
#define TOT (EE + NN)
#define NEG_SLOPE 0.2f

// ---------------- scratch (device globals; no allocation allowed) ----------------
__device__ float g_xl[NN * HD];
__device__ float g_xr[NN * HD];
__device__ float g_hA[NN * HD];
__device__ float g_hB[NN * HD];
__device__ int   g_counts[NN];
__device__ int   g_local[NN];
__device__ int   g_rowptr[NN + 1];
__device__ int   g_cursor[NN];
__device__ int   g_srcarr[TOT];
__device__ int   g_blocksums[64];
__device__ float g_pool[HD];

// buffer selector: 0=xl 1=xr 2=hA 3=hB
__device__ __forceinline__ float* buf(int i) {
    return i == 0 ? g_xl : i == 1 ? g_xr : i == 2 ? g_hA : g_hB;
}

// ---------------- CSR build ----------------
__global__ void k_init() {
    int i = blockIdx.x * blockDim.x + threadIdx.x;
    if (i < NN) g_counts[i] = 1;          // self loop
    if (i < HD) g_pool[i] = 0.f;
}

__global__ void k_hist(const int* __restrict__ ei) {
    int e = blockIdx.x * blockDim.x + threadIdx.x;
    if (e < EE) {
        int d = ei[EE + e];
        atomicAdd(&g_counts[d], 1);
    }
}

__global__ void k_scan_block() {
    __shared__ int sm[1024];
    int i = blockIdx.x * 1024 + threadIdx.x;
    int v = (i < NN) ? g_counts[i] : 0;
    sm[threadIdx.x] = v;
    __syncthreads();
    for (int off = 1; off < 1024; off <<= 1) {
        int t = (threadIdx.x >= off) ? sm[threadIdx.x - off] : 0;
        __syncthreads();
        sm[threadIdx.x] += t;
        __syncthreads();
    }
    if (i < NN) g_local[i] = sm[threadIdx.x] - v;   // exclusive
    if (threadIdx.x == 1023) g_blocksums[blockIdx.x] = sm[1023];
}

__global__ void k_scan_top(int nb) {
    __shared__ int sm[64];
    int t = threadIdx.x;
    int v = (t < nb) ? g_blocksums[t] : 0;
    sm[t] = v;
    __syncthreads();
    for (int off = 1; off < 64; off <<= 1) {
        int u = (t >= off) ? sm[t - off] : 0;
        __syncthreads();
        sm[t] += u;
        __syncthreads();
    }
    if (t < nb) g_blocksums[t] = sm[t] - v;         // exclusive
}

__global__ void k_finalize_csr() {
    int i = blockIdx.x * blockDim.x + threadIdx.x;
    if (i < NN) {
        int off = g_local[i] + g_blocksums[i >> 10];
        g_rowptr[i] = off;
        g_cursor[i] = off + 1;      // slot 0 reserved for self loop
        g_srcarr[off] = i;          // self loop
    }
    if (i == 0) g_rowptr[NN] = TOT;
}

__global__ void k_scatter(const int* __restrict__ ei) {
    int e = blockIdx.x * blockDim.x + threadIdx.x;
    if (e < EE) {
        int s = ei[e];
        int d = ei[EE + e];
        int pos = atomicAdd(&g_cursor[d], 1);
        g_srcarr[pos] = s;
    }
}

// ---------------- SGEMM: C[M,128] = A[M,K] @ B[K,128] ----------------
// Asel < 0: A = Aext (external input); else scratch buffer. C = buf(Csel).
__global__ void k_sgemm128(const float* __restrict__ Aext, int Asel, int Csel,
                           const float* __restrict__ B, int M, int K) {
    const float* __restrict__ A = (Asel < 0) ? Aext : buf(Asel);
    float* __restrict__ C = buf(Csel);

    __shared__ float As[8][128];
    __shared__ float Bs[8][128];
    const int tx = threadIdx.x & 15;
    const int ty = threadIdx.x >> 4;
    const int row0 = blockIdx.x * 128;
    float acc[8][8];
    #pragma unroll
    for (int i = 0; i < 8; i++)
        #pragma unroll
        for (int j = 0; j < 8; j++) acc[i][j] = 0.f;

    for (int k0 = 0; k0 < K; k0 += 8) {
        #pragma unroll
        for (int i = 0; i < 4; i++) {
            int idx = threadIdx.x + i * 256;
            int r = idx >> 3, kk = idx & 7;
            int gr = row0 + r;
            As[kk][r] = (gr < M) ? A[(size_t)gr * K + k0 + kk] : 0.f;
            int kb = idx >> 7, c = idx & 127;
            Bs[kb][c] = B[(size_t)(k0 + kb) * 128 + c];
        }
        __syncthreads();
        #pragma unroll
        for (int kk = 0; kk < 8; kk++) {
            float a[8], b[8];
            #pragma unroll
            for (int i = 0; i < 8; i++) a[i] = As[kk][ty * 8 + i];
            #pragma unroll
            for (int j = 0; j < 8; j++) b[j] = Bs[kk][tx * 8 + j];
            #pragma unroll
            for (int i = 0; i < 8; i++)
                #pragma unroll
                for (int j = 0; j < 8; j++) acc[i][j] += a[i] * b[j];
        }
        __syncthreads();
    }
    for (int i = 0; i < 8; i++) {
        int gr = row0 + ty * 8 + i;
        if (gr >= M) break;
        #pragma unroll
        for (int j = 0; j < 8; j++)
            C[(size_t)gr * 128 + tx * 8 + j] = acc[i][j];
    }
}

// ---------------- GATv2 aggregation: one warp per node, online softmax ----------------
__device__ __forceinline__ float lrelu(float v) { return v > 0.f ? v : NEG_SLOPE * v; }

__global__ void k_aggregate(const float* __restrict__ att, const float* __restrict__ bias,
                            int outsel, int do_relu) {
    int warp = (blockIdx.x * blockDim.x + threadIdx.x) >> 5;
    if (warp >= NN) return;
    int lane = threadIdx.x & 31;
    const float* __restrict__ xl = g_xl;
    const float* __restrict__ xr = g_xr;
    float* __restrict__ out = buf(outsel);

    const float4 xrv  = *reinterpret_cast<const float4*>(&xr[(size_t)warp * HD + lane * 4]);
    const float4 attv = *reinterpret_cast<const float4*>(&att[lane * 4]);

    float m = -1e30f, s = 0.f;
    float4 acc = make_float4(0.f, 0.f, 0.f, 0.f);

    int beg = g_rowptr[warp];
    int end = g_rowptr[warp + 1];
    for (int e = beg; e < end; e++) {
        int sn = g_srcarr[e];
        const float4 xlv = *reinterpret_cast<const float4*>(&xl[(size_t)sn * HD + lane * 4]);
        float p = lrelu(xlv.x + xrv.x) * attv.x
                + lrelu(xlv.y + xrv.y) * attv.y
                + lrelu(xlv.z + xrv.z) * attv.z
                + lrelu(xlv.w + xrv.w) * attv.w;
        // reduce over the 8 lanes of this head
        p += __shfl_xor_sync(0xffffffffu, p, 1);
        p += __shfl_xor_sync(0xffffffffu, p, 2);
        p += __shfl_xor_sync(0xffffffffu, p, 4);
        float eh = p;
        if (eh > m) {
            float sc = __expf(m - eh);
            s *= sc;
            acc.x *= sc; acc.y *= sc; acc.z *= sc; acc.w *= sc;
            m = eh;
        }
        float w = __expf(eh - m);
        s += w;
        acc.x += w * xlv.x; acc.y += w * xlv.y;
        acc.z += w * xlv.z; acc.w += w * xlv.w;
    }
    float inv = 1.f / (s + 1e-16f);
    const float4 bv = *reinterpret_cast<const float4*>(&bias[lane * 4]);
    float4 o;
    o.x = acc.x * inv + bv.x;
    o.y = acc.y * inv + bv.y;
    o.z = acc.z * inv + bv.z;
    o.w = acc.w * inv + bv.w;
    if (do_relu) {
        o.x = fmaxf(o.x, 0.f); o.y = fmaxf(o.y, 0.f);
        o.z = fmaxf(o.z, 0.f); o.w = fmaxf(o.w, 0.f);
    }
    *reinterpret_cast<float4*>(&out[(size_t)warp * HD + lane * 4]) = o;
}

// ---------------- pooling + classifier ----------------
__global__ void k_pool(int hsel) {
    const float* __restrict__ h = buf(hsel);
    int col = threadIdx.x;   // blockDim = 128
    float acc = 0.f;
    for (int r = blockIdx.x; r < NN; r += gridDim.x)
        acc += h[(size_t)r * HD + col];
    atomicAdd(&g_pool[col], acc);
}

__global__ void k_classify(const float* __restrict__ W, const float* __restrict__ b,
                           float* __restrict__ out) {
    int j = threadIdx.x;
    if (j < 2) {
        float s = 0.f;
        const float invn = 1.f / (float)NN;
        for (int k = 0; k < HD; k++)
            s += g_pool[k] * invn * W[k * 2 + j];
        out[j] = s + b[j];
    }
}

// ---------------- launch ----------------
extern "C" void kernel_launch(void* const* d_in, const int* in_sizes, int n_in,
                              void* d_out, int out_size) {
    const float* x  = (const float*)d_in[0];
    const int*   ei = (const int*)d_in[1];   // int64 in reference, but JAX x64 is
                                             // disabled -> delivered as int32
    const float* Wl[4]  = {(const float*)d_in[2],  (const float*)d_in[6],
                           (const float*)d_in[10], (const float*)d_in[14]};
    const float* Wr[4]  = {(const float*)d_in[3],  (const float*)d_in[7],
                           (const float*)d_in[11], (const float*)d_in[15]};
    const float* att[4] = {(const float*)d_in[4],  (const float*)d_in[8],
                           (const float*)d_in[12], (const float*)d_in[16]};
    const float* bia[4] = {(const float*)d_in[5],  (const float*)d_in[9],
                           (const float*)d_in[13], (const float*)d_in[17]};
    const float* clfW = (const float*)d_in[18];
    const float* clfb = (const float*)d_in[19];
    float* out = (float*)d_out;

    const int TB = 256;
    const int gN  = (NN + TB - 1) / TB;
    const int gE  = (EE + TB - 1) / TB;
    const int gSc = (NN + 1023) / 1024;            // 49
    const int gGm = (NN + 127) / 128;              // 391
    const int gAg = (NN * 32 + TB - 1) / TB;       // warp per node

    // CSR by dst (rebuilt every call: deterministic work)
    k_init<<<gN, TB>>>();
    k_hist<<<gE, TB>>>(ei);
    k_scan_block<<<gSc, 1024>>>();
    k_scan_top<<<1, 64>>>(gSc);
    k_finalize_csr<<<gN, TB>>>();
    k_scatter<<<gE, TB>>>(ei);

    // layer 1 (K=768): A = external x
    k_sgemm128<<<gGm, TB>>>(x, -1, 0, Wl[0], NN, FIN);
    k_sgemm128<<<gGm, TB>>>(x, -1, 1, Wr[0], NN, FIN);
    k_aggregate<<<gAg, TB>>>(att[0], bia[0], 2, 1);
    // layer 2: A = hA(2)
    k_sgemm128<<<gGm, TB>>>(nullptr, 2, 0, Wl[1], NN, HD);
    k_sgemm128<<<gGm, TB>>>(nullptr, 2, 1, Wr[1], NN, HD);
    k_aggregate<<<gAg, TB>>>(att[1], bia[1], 3, 1);
    // layer 3: A = hB(3)
    k_sgemm128<<<gGm, TB>>>(nullptr, 3, 0, Wl[2], NN, HD);
    k_sgemm128<<<gGm, TB>>>(nullptr, 3, 1, Wr[2], NN, HD);
    k_aggregate<<<gAg, TB>>>(att[2], bia[2], 2, 1);
    // layer 4 (no relu): A = hA(2)
    k_sgemm128<<<gGm, TB>>>(nullptr, 2, 0, Wl[3], NN, HD);
    k_sgemm128<<<gGm, TB>>>(nullptr, 2, 1, Wr[3], NN, HD);
    k_aggregate<<<gAg, TB>>>(att[3], bia[3], 3, 0);

    // mean-pool + classifier
    k_pool<<<512, 128>>>(3);
    k_classify<<<1, 32>>>(clfW, clfb, out);
}

// round 4
// speedup vs baseline: 2.3442x; 2.3442x over previous
#include <cuda_runtime.h>
#include <cstdint>

#define NN 50000
#define EE 640000
#define FIN 768
#define HD 128
#define TOT (EE + NN)
#define NEG_SLOPE 0.2f

// ---------------- scratch (device globals; no allocation allowed) ----------------
__device__ float g_xl[NN * HD];
__device__ float g_xr[NN * HD];
__device__ float g_hA[NN * HD];
__device__ float g_hB[NN * HD];
__device__ int   g_counts[NN];
__device__ int   g_local[NN];
__device__ int   g_rowptr[NN + 1];
__device__ int   g_cursor[NN];
__device__ int   g_srcarr[TOT];
__device__ int   g_blocksums[64];
__device__ float g_pool[HD];

// buffer selector: 0=xl 1=xr 2=hA 3=hB
__device__ __forceinline__ float* buf(int i) {
    return i == 0 ? g_xl : i == 1 ? g_xr : i == 2 ? g_hA : g_hB;
}

// ---------------- CSR build ----------------
__global__ void k_init() {
    int i = blockIdx.x * blockDim.x + threadIdx.x;
    if (i < NN) g_counts[i] = 1;          // self loop
    if (i < HD) g_pool[i] = 0.f;
}

__global__ void k_hist(const int* __restrict__ ei) {
    int e = blockIdx.x * blockDim.x + threadIdx.x;
    if (e < EE) {
        int d = ei[EE + e];
        atomicAdd(&g_counts[d], 1);
    }
}

__global__ void k_scan_block() {
    __shared__ int sm[1024];
    int i = blockIdx.x * 1024 + threadIdx.x;
    int v = (i < NN) ? g_counts[i] : 0;
    sm[threadIdx.x] = v;
    __syncthreads();
    for (int off = 1; off < 1024; off <<= 1) {
        int t = (threadIdx.x >= off) ? sm[threadIdx.x - off] : 0;
        __syncthreads();
        sm[threadIdx.x] += t;
        __syncthreads();
    }
    if (i < NN) g_local[i] = sm[threadIdx.x] - v;   // exclusive
    if (threadIdx.x == 1023) g_blocksums[blockIdx.x] = sm[1023];
}

__global__ void k_scan_top(int nb) {
    __shared__ int sm[64];
    int t = threadIdx.x;
    int v = (t < nb) ? g_blocksums[t] : 0;
    sm[t] = v;
    __syncthreads();
    for (int off = 1; off < 64; off <<= 1) {
        int u = (t >= off) ? sm[t - off] : 0;
        __syncthreads();
        sm[t] += u;
        __syncthreads();
    }
    if (t < nb) g_blocksums[t] = sm[t] - v;         // exclusive
}

__global__ void k_finalize_csr() {
    int i = blockIdx.x * blockDim.x + threadIdx.x;
    if (i < NN) {
        int off = g_local[i] + g_blocksums[i >> 10];
        g_rowptr[i] = off;
        g_cursor[i] = off + 1;      // slot 0 reserved for self loop
        g_srcarr[off] = i;          // self loop
    }
    if (i == 0) g_rowptr[NN] = TOT;
}

__global__ void k_scatter(const int* __restrict__ ei) {
    int e = blockIdx.x * blockDim.x + threadIdx.x;
    if (e < EE) {
        int s = ei[e];
        int d = ei[EE + e];
        int pos = atomicAdd(&g_cursor[d], 1);
        g_srcarr[pos] = s;
    }
}

// ---------------- tf32 tensor-core GEMM: C[M,128] = A[M,K] @ B[K,128] ----------------
__device__ __forceinline__ uint32_t to_tf32(float x) {
    uint32_t r;
    asm("cvt.rna.tf32.f32 %0, %1;" : "=r"(r) : "f"(x));
    return r;
}

#define AS_STRIDE 36    // 36 mod 32 = 4 -> A-frag loads conflict-free
#define BS_STRIDE 136   // 136 mod 32 = 8 -> B-frag loads conflict-free

__global__ void __launch_bounds__(256, 2)
k_mma_gemm(const float* __restrict__ Aext, int Asel, int Csel,
           const float* __restrict__ B, int M, int K) {
    const float* __restrict__ A = (Asel < 0) ? Aext : buf(Asel);
    float* __restrict__ C = buf(Csel);

    __shared__ uint32_t As[128 * AS_STRIDE];  // [row][k], row-major, tf32 bits
    __shared__ uint32_t Bs[32 * BS_STRIDE];   // [k][n],   k-major,   tf32 bits

    const int tid  = threadIdx.x;
    const int wid  = tid >> 5;
    const int lane = tid & 31;
    const int g = lane >> 2;     // group id (0..7)
    const int t = lane & 3;      // thread in group (0..3)
    const int warpM = wid & 1;   // 2 warps in M (64 rows each)
    const int warpN = wid >> 1;  // 4 warps in N (32 cols each)
    const int row0 = blockIdx.x * 128;

    float acc[4][4][4];
    #pragma unroll
    for (int i = 0; i < 4; i++)
        #pragma unroll
        for (int j = 0; j < 4; j++)
            #pragma unroll
            for (int k = 0; k < 4; k++) acc[i][j][k] = 0.f;

    for (int k0 = 0; k0 < K; k0 += 32) {
        // stage A tile [128 x 32], converting to tf32
        #pragma unroll
        for (int i = 0; i < 4; i++) {
            int idx = tid + i * 256;     // 0..1023 float4 slots
            int r  = idx >> 3;           // 0..127
            int kq = idx & 7;            // which float4 along k
            int gr = row0 + r;
            float4 v = make_float4(0.f, 0.f, 0.f, 0.f);
            if (gr < M) v = *reinterpret_cast<const float4*>(&A[(size_t)gr * K + k0 + kq * 4]);
            uint32_t* dst = &As[r * AS_STRIDE + kq * 4];
            dst[0] = to_tf32(v.x); dst[1] = to_tf32(v.y);
            dst[2] = to_tf32(v.z); dst[3] = to_tf32(v.w);
        }
        // stage B tile [32 x 128], converting to tf32
        #pragma unroll
        for (int i = 0; i < 4; i++) {
            int idx = tid + i * 256;
            int kk = idx >> 5;           // 0..31
            int nq = idx & 31;           // which float4 along n
            float4 v = *reinterpret_cast<const float4*>(&B[(size_t)(k0 + kk) * 128 + nq * 4]);
            uint32_t* dst = &Bs[kk * BS_STRIDE + nq * 4];
            dst[0] = to_tf32(v.x); dst[1] = to_tf32(v.y);
            dst[2] = to_tf32(v.z); dst[3] = to_tf32(v.w);
        }
        __syncthreads();

        #pragma unroll
        for (int ks = 0; ks < 32; ks += 8) {
            uint32_t afr[4][4];
            #pragma unroll
            for (int mt = 0; mt < 4; mt++) {
                int rowb = warpM * 64 + mt * 16;
                afr[mt][0] = As[(rowb + g)     * AS_STRIDE + ks + t];
                afr[mt][1] = As[(rowb + g + 8) * AS_STRIDE + ks + t];
                afr[mt][2] = As[(rowb + g)     * AS_STRIDE + ks + t + 4];
                afr[mt][3] = As[(rowb + g + 8) * AS_STRIDE + ks + t + 4];
            }
            uint32_t bfr[4][2];
            #pragma unroll
            for (int nt = 0; nt < 4; nt++) {
                int nb = warpN * 32 + nt * 8;
                bfr[nt][0] = Bs[(ks + t)     * BS_STRIDE + nb + g];
                bfr[nt][1] = Bs[(ks + t + 4) * BS_STRIDE + nb + g];
            }
            #pragma unroll
            for (int mt = 0; mt < 4; mt++)
                #pragma unroll
                for (int nt = 0; nt < 4; nt++) {
                    asm volatile(
                        "mma.sync.aligned.m16n8k8.row.col.f32.tf32.tf32.f32 "
                        "{%0,%1,%2,%3}, {%4,%5,%6,%7}, {%8,%9}, {%0,%1,%2,%3};"
                        : "+f"(acc[mt][nt][0]), "+f"(acc[mt][nt][1]),
                          "+f"(acc[mt][nt][2]), "+f"(acc[mt][nt][3])
                        : "r"(afr[mt][0]), "r"(afr[mt][1]), "r"(afr[mt][2]), "r"(afr[mt][3]),
                          "r"(bfr[nt][0]), "r"(bfr[nt][1]));
                }
        }
        __syncthreads();
    }

    // epilogue
    #pragma unroll
    for (int mt = 0; mt < 4; mt++) {
        int r0 = row0 + warpM * 64 + mt * 16 + g;
        #pragma unroll
        for (int nt = 0; nt < 4; nt++) {
            int c = warpN * 32 + nt * 8 + t * 2;
            if (r0 < M)
                *reinterpret_cast<float2*>(&C[(size_t)r0 * 128 + c]) =
                    make_float2(acc[mt][nt][0], acc[mt][nt][1]);
            if (r0 + 8 < M)
                *reinterpret_cast<float2*>(&C[(size_t)(r0 + 8) * 128 + c]) =
                    make_float2(acc[mt][nt][2], acc[mt][nt][3]);
        }
    }
}

// ---------------- GATv2 aggregation: one warp per node, online softmax ----------------
__device__ __forceinline__ float lrelu(float v) { return v > 0.f ? v : NEG_SLOPE * v; }

__global__ void k_aggregate(const float* __restrict__ att, const float* __restrict__ bias,
                            int outsel, int do_relu) {
    int warp = (blockIdx.x * blockDim.x + threadIdx.x) >> 5;
    if (warp >= NN) return;
    int lane = threadIdx.x & 31;
    const float* __restrict__ xl = g_xl;
    const float* __restrict__ xr = g_xr;
    float* __restrict__ out = buf(outsel);

    const float4 xrv  = *reinterpret_cast<const float4*>(&xr[(size_t)warp * HD + lane * 4]);
    const float4 attv = *reinterpret_cast<const float4*>(&att[lane * 4]);

    float m = -1e30f, s = 0.f;
    float4 acc = make_float4(0.f, 0.f, 0.f, 0.f);

    int beg = g_rowptr[warp];
    int end = g_rowptr[warp + 1];
    for (int e = beg; e < end; e++) {
        int sn = g_srcarr[e];
        const float4 xlv = *reinterpret_cast<const float4*>(&xl[(size_t)sn * HD + lane * 4]);
        float p = lrelu(xlv.x + xrv.x) * attv.x
                + lrelu(xlv.y + xrv.y) * attv.y
                + lrelu(xlv.z + xrv.z) * attv.z
                + lrelu(xlv.w + xrv.w) * attv.w;
        p += __shfl_xor_sync(0xffffffffu, p, 1);
        p += __shfl_xor_sync(0xffffffffu, p, 2);
        p += __shfl_xor_sync(0xffffffffu, p, 4);
        float eh = p;
        if (eh > m) {
            float sc = __expf(m - eh);
            s *= sc;
            acc.x *= sc; acc.y *= sc; acc.z *= sc; acc.w *= sc;
            m = eh;
        }
        float w = __expf(eh - m);
        s += w;
        acc.x += w * xlv.x; acc.y += w * xlv.y;
        acc.z += w * xlv.z; acc.w += w * xlv.w;
    }
    float inv = 1.f / (s + 1e-16f);
    const float4 bv = *reinterpret_cast<const float4*>(&bias[lane * 4]);
    float4 o;
    o.x = acc.x * inv + bv.x;
    o.y = acc.y * inv + bv.y;
    o.z = acc.z * inv + bv.z;
    o.w = acc.w * inv + bv.w;
    if (do_relu) {
        o.x = fmaxf(o.x, 0.f); o.y = fmaxf(o.y, 0.f);
        o.z = fmaxf(o.z, 0.f); o.w = fmaxf(o.w, 0.f);
    }
    *reinterpret_cast<float4*>(&out[(size_t)warp * HD + lane * 4]) = o;
}

// ---------------- pooling + classifier ----------------
__global__ void k_pool(int hsel) {
    const float* __restrict__ h = buf(hsel);
    int col = threadIdx.x;   // blockDim = 128
    float acc = 0.f;
    for (int r = blockIdx.x; r < NN; r += gridDim.x)
        acc += h[(size_t)r * HD + col];
    atomicAdd(&g_pool[col], acc);
}

__global__ void k_classify(const float* __restrict__ W, const float* __restrict__ b,
                           float* __restrict__ out) {
    int j = threadIdx.x;
    if (j < 2) {
        float s = 0.f;
        const float invn = 1.f / (float)NN;
        for (int k = 0; k < HD; k++)
            s += g_pool[k] * invn * W[k * 2 + j];
        out[j] = s + b[j];
    }
}

// ---------------- launch ----------------
extern "C" void kernel_launch(void* const* d_in, const int* in_sizes, int n_in,
                              void* d_out, int out_size) {
    const float* x  = (const float*)d_in[0];
    const int*   ei = (const int*)d_in[1];   // delivered as int32 (JAX x64 disabled)
    const float* Wl[4]  = {(const float*)d_in[2],  (const float*)d_in[6],
                           (const float*)d_in[10], (const float*)d_in[14]};
    const float* Wr[4]  = {(const float*)d_in[3],  (const float*)d_in[7],
                           (const float*)d_in[11], (const float*)d_in[15]};
    const float* att[4] = {(const float*)d_in[4],  (const float*)d_in[8],
                           (const float*)d_in[12], (const float*)d_in[16]};
    const float* bia[4] = {(const float*)d_in[5],  (const float*)d_in[9],
                           (const float*)d_in[13], (const float*)d_in[17]};
    const float* clfW = (const float*)d_in[18];
    const float* clfb = (const float*)d_in[19];
    float* out = (float*)d_out;

    const int TB = 256;
    const int gN  = (NN + TB - 1) / TB;
    const int gE  = (EE + TB - 1) / TB;
    const int gSc = (NN + 1023) / 1024;            // 49
    const int gGm = (NN + 127) / 128;              // 391
    const int gAg = (NN * 32 + TB - 1) / TB;       // warp per node

    // CSR by dst (rebuilt every call: deterministic work)
    k_init<<<gN, TB>>>();
    k_hist<<<gE, TB>>>(ei);
    k_scan_block<<<gSc, 1024>>>();
    k_scan_top<<<1, 64>>>(gSc);
    k_finalize_csr<<<gN, TB>>>();
    k_scatter<<<gE, TB>>>(ei);

    // layer 1 (K=768): A = external x
    k_mma_gemm<<<gGm, TB>>>(x, -1, 0, Wl[0], NN, FIN);
    k_mma_gemm<<<gGm, TB>>>(x, -1, 1, Wr[0], NN, FIN);
    k_aggregate<<<gAg, TB>>>(att[0], bia[0], 2, 1);
    // layer 2: A = hA(2)
    k_mma_gemm<<<gGm, TB>>>(nullptr, 2, 0, Wl[1], NN, HD);
    k_mma_gemm<<<gGm, TB>>>(nullptr, 2, 1, Wr[1], NN, HD);
    k_aggregate<<<gAg, TB>>>(att[1], bia[1], 3, 1);
    // layer 3: A = hB(3)
    k_mma_gemm<<<gGm, TB>>>(nullptr, 3, 0, Wl[2], NN, HD);
    k_mma_gemm<<<gGm, TB>>>(nullptr, 3, 1, Wr[2], NN, HD);
    k_aggregate<<<gAg, TB>>>(att[2], bia[2], 2, 1);
    // layer 4 (no relu): A = hA(2)
    k_mma_gemm<<<gGm, TB>>>(nullptr, 2, 0, Wl[3], NN, HD);
    k_mma_gemm<<<gGm, TB>>>(nullptr, 2, 1, Wr[3], NN, HD);
    k_aggregate<<<gAg, TB>>>(att[3], bia[3], 3, 0);

    // mean-pool + classifier
    k_pool<<<512, 128>>>(3);
    k_classify<<<1, 32>>>(clfW, clfb, out);
}

// round 5
// speedup vs baseline: 2.6613x; 1.1353x over previous
#include <cuda_runtime.h>
#include <cstdint>

#define NN 50000
#define EE 640000
#define FIN 768
#define HD 128
#define TOT (EE + NN)
#define NEG_SLOPE 0.2f

// ---------------- scratch (device globals; no allocation allowed) ----------------
__device__ float g_xl[NN * HD];
__device__ float g_xr[NN * HD];
__device__ float g_hA[NN * HD];
__device__ float g_hB[NN * HD];
__device__ int   g_counts[NN];
__device__ int   g_local[NN];
__device__ int   g_rowptr[NN + 1];
__device__ int   g_cursor[NN];
__device__ int   g_srcarr[TOT];
__device__ int   g_blocksums[64];
__device__ float g_pool[HD];

// buffer selector: 0=xl 1=xr 2=hA 3=hB
__device__ __forceinline__ float* buf(int i) {
    return i == 0 ? g_xl : i == 1 ? g_xr : i == 2 ? g_hA : g_hB;
}

// ---------------- CSR build ----------------
__global__ void k_init() {
    int i = blockIdx.x * blockDim.x + threadIdx.x;
    if (i < NN) g_counts[i] = 1;          // self loop
    if (i < HD) g_pool[i] = 0.f;
}

__global__ void k_hist(const int* __restrict__ ei) {
    int e = blockIdx.x * blockDim.x + threadIdx.x;
    if (e < EE) {
        int d = ei[EE + e];
        atomicAdd(&g_counts[d], 1);
    }
}

__global__ void k_scan_block() {
    __shared__ int sm[1024];
    int i = blockIdx.x * 1024 + threadIdx.x;
    int v = (i < NN) ? g_counts[i] : 0;
    sm[threadIdx.x] = v;
    __syncthreads();
    for (int off = 1; off < 1024; off <<= 1) {
        int t = (threadIdx.x >= off) ? sm[threadIdx.x - off] : 0;
        __syncthreads();
        sm[threadIdx.x] += t;
        __syncthreads();
    }
    if (i < NN) g_local[i] = sm[threadIdx.x] - v;   // exclusive
    if (threadIdx.x == 1023) g_blocksums[blockIdx.x] = sm[1023];
}

__global__ void k_scan_top(int nb) {
    __shared__ int sm[64];
    int t = threadIdx.x;
    int v = (t < nb) ? g_blocksums[t] : 0;
    sm[t] = v;
    __syncthreads();
    for (int off = 1; off < 64; off <<= 1) {
        int u = (t >= off) ? sm[t - off] : 0;
        __syncthreads();
        sm[t] += u;
        __syncthreads();
    }
    if (t < nb) g_blocksums[t] = sm[t] - v;         // exclusive
}

__global__ void k_finalize_csr() {
    int i = blockIdx.x * blockDim.x + threadIdx.x;
    if (i < NN) {
        int off = g_local[i] + g_blocksums[i >> 10];
        g_rowptr[i] = off;
        g_cursor[i] = off + 1;      // slot 0 reserved for self loop
        g_srcarr[off] = i;          // self loop
    }
    if (i == 0) g_rowptr[NN] = TOT;
}

__global__ void k_scatter(const int* __restrict__ ei) {
    int e = blockIdx.x * blockDim.x + threadIdx.x;
    if (e < EE) {
        int s = ei[e];
        int d = ei[EE + e];
        int pos = atomicAdd(&g_cursor[d], 1);
        g_srcarr[pos] = s;
    }
}

// ---------------- tf32 tensor-core dual GEMM ----------------
// Computes BOTH  xl = A @ B1  and  xr = A @ B2  in one launch.
// Grid: 2 * ceil(M/128) blocks; lower half -> B1/xl, upper half -> B2/xr.
// K-chunk 16, double-buffered smem, register-staged global loads.
__device__ __forceinline__ uint32_t to_tf32(float x) {
    uint32_t r;
    asm("cvt.rna.tf32.f32 %0, %1;" : "=r"(r) : "f"(x));
    return r;
}

#define AS_STRIDE 20    // 20 mod 32 = 20; rows g*20+t distinct banks -> conflict-free
#define BS_STRIDE 136   // 136 mod 32 = 8  -> conflict-free

__global__ void __launch_bounds__(256, 2)
k_mma_dual(const float* __restrict__ Aext, int Asel,
           const float* __restrict__ B1, const float* __restrict__ B2,
           int M, int K) {
    const float* __restrict__ A = (Asel < 0) ? Aext : buf(Asel);

    const int nb   = gridDim.x >> 1;
    const int half = (blockIdx.x >= nb) ? 1 : 0;
    const int blk  = blockIdx.x - half * nb;
    const float* __restrict__ B = half ? B2 : B1;
    float* __restrict__ C = half ? g_xr : g_xl;

    __shared__ uint32_t As[2][128 * AS_STRIDE];
    __shared__ uint32_t Bs[2][16 * BS_STRIDE];

    const int tid  = threadIdx.x;
    const int wid  = tid >> 5;
    const int lane = tid & 31;
    const int g = lane >> 2;
    const int t = lane & 3;
    const int warpM = wid & 1;   // 2 warps in M (64 rows each)
    const int warpN = wid >> 1;  // 4 warps in N (32 cols each)
    const int row0 = blk * 128;

    float acc[4][4][4];
    #pragma unroll
    for (int i = 0; i < 4; i++)
        #pragma unroll
        for (int j = 0; j < 4; j++)
            #pragma unroll
            for (int k = 0; k < 4; k++) acc[i][j][k] = 0.f;

    // staging registers (tile i+1)
    float4 ra[2], rb[2];

    // ---- load tile 0 ----
    #pragma unroll
    for (int i = 0; i < 2; i++) {
        int idx = tid + i * 256;          // A: 512 float4 slots
        int r  = idx >> 2, kq = idx & 3;
        int gr = row0 + r;
        ra[i] = (gr < M) ? *reinterpret_cast<const float4*>(&A[(size_t)gr * K + kq * 4])
                         : make_float4(0.f, 0.f, 0.f, 0.f);
        int kk = idx >> 5, nq = idx & 31; // B: 512 float4 slots
        rb[i] = *reinterpret_cast<const float4*>(&B[(size_t)kk * 128 + nq * 4]);
    }
    // store tile 0 -> buffer 0
    #pragma unroll
    for (int i = 0; i < 2; i++) {
        int idx = tid + i * 256;
        int r  = idx >> 2, kq = idx & 3;
        uint32_t* da = &As[0][r * AS_STRIDE + kq * 4];
        da[0] = to_tf32(ra[i].x); da[1] = to_tf32(ra[i].y);
        da[2] = to_tf32(ra[i].z); da[3] = to_tf32(ra[i].w);
        int kk = idx >> 5, nq = idx & 31;
        uint32_t* db = &Bs[0][kk * BS_STRIDE + nq * 4];
        db[0] = to_tf32(rb[i].x); db[1] = to_tf32(rb[i].y);
        db[2] = to_tf32(rb[i].z); db[3] = to_tf32(rb[i].w);
    }
    __syncthreads();

    const int niter = K >> 4;
    int cur = 0;
    for (int it = 0; it < niter; it++) {
        const bool has_next = (it + 1 < niter);
        const int k0n = (it + 1) << 4;
        if (has_next) {
            #pragma unroll
            for (int i = 0; i < 2; i++) {
                int idx = tid + i * 256;
                int r  = idx >> 2, kq = idx & 3;
                int gr = row0 + r;
                ra[i] = (gr < M) ? *reinterpret_cast<const float4*>(&A[(size_t)gr * K + k0n + kq * 4])
                                 : make_float4(0.f, 0.f, 0.f, 0.f);
                int kk = idx >> 5, nq = idx & 31;
                rb[i] = *reinterpret_cast<const float4*>(&B[(size_t)(k0n + kk) * 128 + nq * 4]);
            }
        }

        // compute on buffer `cur`
        const uint32_t* __restrict__ Ab = As[cur];
        const uint32_t* __restrict__ Bb = Bs[cur];
        #pragma unroll
        for (int ks = 0; ks < 16; ks += 8) {
            uint32_t afr[4][4];
            #pragma unroll
            for (int mt = 0; mt < 4; mt++) {
                int rowb = warpM * 64 + mt * 16;
                afr[mt][0] = Ab[(rowb + g)     * AS_STRIDE + ks + t];
                afr[mt][1] = Ab[(rowb + g + 8) * AS_STRIDE + ks + t];
                afr[mt][2] = Ab[(rowb + g)     * AS_STRIDE + ks + t + 4];
                afr[mt][3] = Ab[(rowb + g + 8) * AS_STRIDE + ks + t + 4];
            }
            uint32_t bfr[4][2];
            #pragma unroll
            for (int nt = 0; nt < 4; nt++) {
                int nbase = warpN * 32 + nt * 8;
                bfr[nt][0] = Bb[(ks + t)     * BS_STRIDE + nbase + g];
                bfr[nt][1] = Bb[(ks + t + 4) * BS_STRIDE + nbase + g];
            }
            #pragma unroll
            for (int mt = 0; mt < 4; mt++)
                #pragma unroll
                for (int nt = 0; nt < 4; nt++) {
                    asm volatile(
                        "mma.sync.aligned.m16n8k8.row.col.f32.tf32.tf32.f32 "
                        "{%0,%1,%2,%3}, {%4,%5,%6,%7}, {%8,%9}, {%0,%1,%2,%3};"
                        : "+f"(acc[mt][nt][0]), "+f"(acc[mt][nt][1]),
                          "+f"(acc[mt][nt][2]), "+f"(acc[mt][nt][3])
                        : "r"(afr[mt][0]), "r"(afr[mt][1]), "r"(afr[mt][2]), "r"(afr[mt][3]),
                          "r"(bfr[nt][0]), "r"(bfr[nt][1]));
                }
        }

        if (has_next) {
            // write buffer cur^1 (last read one full iteration ago, sync below protects)
            int nxt = cur ^ 1;
            #pragma unroll
            for (int i = 0; i < 2; i++) {
                int idx = tid + i * 256;
                int r  = idx >> 2, kq = idx & 3;
                uint32_t* da = &As[nxt][r * AS_STRIDE + kq * 4];
                da[0] = to_tf32(ra[i].x); da[1] = to_tf32(ra[i].y);
                da[2] = to_tf32(ra[i].z); da[3] = to_tf32(ra[i].w);
                int kk = idx >> 5, nq = idx & 31;
                uint32_t* db = &Bs[nxt][kk * BS_STRIDE + nq * 4];
                db[0] = to_tf32(rb[i].x); db[1] = to_tf32(rb[i].y);
                db[2] = to_tf32(rb[i].z); db[3] = to_tf32(rb[i].w);
            }
        }
        __syncthreads();
        cur ^= 1;
    }

    // epilogue
    #pragma unroll
    for (int mt = 0; mt < 4; mt++) {
        int r0 = row0 + warpM * 64 + mt * 16 + g;
        #pragma unroll
        for (int nt = 0; nt < 4; nt++) {
            int c = warpN * 32 + nt * 8 + t * 2;
            if (r0 < M)
                *reinterpret_cast<float2*>(&C[(size_t)r0 * 128 + c]) =
                    make_float2(acc[mt][nt][0], acc[mt][nt][1]);
            if (r0 + 8 < M)
                *reinterpret_cast<float2*>(&C[(size_t)(r0 + 8) * 128 + c]) =
                    make_float2(acc[mt][nt][2], acc[mt][nt][3]);
        }
    }
}

// ---------------- GATv2 aggregation: one warp per node, online softmax ----------------
__device__ __forceinline__ float lrelu(float v) { return v > 0.f ? v : NEG_SLOPE * v; }

__global__ void k_aggregate(const float* __restrict__ att, const float* __restrict__ bias,
                            int outsel, int do_relu) {
    int warp = (blockIdx.x * blockDim.x + threadIdx.x) >> 5;
    if (warp >= NN) return;
    int lane = threadIdx.x & 31;
    const float* __restrict__ xl = g_xl;
    const float* __restrict__ xr = g_xr;
    float* __restrict__ out = buf(outsel);

    const float4 xrv  = *reinterpret_cast<const float4*>(&xr[(size_t)warp * HD + lane * 4]);
    const float4 attv = *reinterpret_cast<const float4*>(&att[lane * 4]);

    float m = -1e30f, s = 0.f;
    float4 acc = make_float4(0.f, 0.f, 0.f, 0.f);

    const int beg = g_rowptr[warp];
    const int end = g_rowptr[warp + 1];

    // software pipeline: load edge e+1 while processing edge e
    float4 nxt = *reinterpret_cast<const float4*>(
        &xl[(size_t)g_srcarr[beg] * HD + lane * 4]);
    for (int e = beg; e < end; e++) {
        float4 xlv = nxt;
        if (e + 1 < end) {
            int s2 = g_srcarr[e + 1];
            nxt = *reinterpret_cast<const float4*>(&xl[(size_t)s2 * HD + lane * 4]);
        }
        float p = lrelu(xlv.x + xrv.x) * attv.x
                + lrelu(xlv.y + xrv.y) * attv.y
                + lrelu(xlv.z + xrv.z) * attv.z
                + lrelu(xlv.w + xrv.w) * attv.w;
        p += __shfl_xor_sync(0xffffffffu, p, 1);
        p += __shfl_xor_sync(0xffffffffu, p, 2);
        p += __shfl_xor_sync(0xffffffffu, p, 4);
        float eh = p;
        if (eh > m) {
            float sc = __expf(m - eh);
            s *= sc;
            acc.x *= sc; acc.y *= sc; acc.z *= sc; acc.w *= sc;
            m = eh;
        }
        float w = __expf(eh - m);
        s += w;
        acc.x += w * xlv.x; acc.y += w * xlv.y;
        acc.z += w * xlv.z; acc.w += w * xlv.w;
    }
    float inv = 1.f / (s + 1e-16f);
    const float4 bv = *reinterpret_cast<const float4*>(&bias[lane * 4]);
    float4 o;
    o.x = acc.x * inv + bv.x;
    o.y = acc.y * inv + bv.y;
    o.z = acc.z * inv + bv.z;
    o.w = acc.w * inv + bv.w;
    if (do_relu) {
        o.x = fmaxf(o.x, 0.f); o.y = fmaxf(o.y, 0.f);
        o.z = fmaxf(o.z, 0.f); o.w = fmaxf(o.w, 0.f);
    }
    *reinterpret_cast<float4*>(&out[(size_t)warp * HD + lane * 4]) = o;
}

// ---------------- pooling + classifier ----------------
__global__ void k_pool(int hsel) {
    const float* __restrict__ h = buf(hsel);
    int col = threadIdx.x;   // blockDim = 128
    float acc = 0.f;
    for (int r = blockIdx.x; r < NN; r += gridDim.x)
        acc += h[(size_t)r * HD + col];
    atomicAdd(&g_pool[col], acc);
}

__global__ void k_classify(const float* __restrict__ W, const float* __restrict__ b,
                           float* __restrict__ out) {
    int j = threadIdx.x;
    if (j < 2) {
        float s = 0.f;
        const float invn = 1.f / (float)NN;
        for (int k = 0; k < HD; k++)
            s += g_pool[k] * invn * W[k * 2 + j];
        out[j] = s + b[j];
    }
}

// ---------------- launch ----------------
extern "C" void kernel_launch(void* const* d_in, const int* in_sizes, int n_in,
                              void* d_out, int out_size) {
    const float* x  = (const float*)d_in[0];
    const int*   ei = (const int*)d_in[1];   // delivered as int32 (JAX x64 disabled)
    const float* Wl[4]  = {(const float*)d_in[2],  (const float*)d_in[6],
                           (const float*)d_in[10], (const float*)d_in[14]};
    const float* Wr[4]  = {(const float*)d_in[3],  (const float*)d_in[7],
                           (const float*)d_in[11], (const float*)d_in[15]};
    const float* att[4] = {(const float*)d_in[4],  (const float*)d_in[8],
                           (const float*)d_in[12], (const float*)d_in[16]};
    const float* bia[4] = {(const float*)d_in[5],  (const float*)d_in[9],
                           (const float*)d_in[13], (const float*)d_in[17]};
    const float* clfW = (const float*)d_in[18];
    const float* clfb = (const float*)d_in[19];
    float* out = (float*)d_out;

    const int TB = 256;
    const int gN  = (NN + TB - 1) / TB;
    const int gE  = (EE + TB - 1) / TB;
    const int gSc = (NN + 1023) / 1024;            // 49
    const int gGm = 2 * ((NN + 127) / 128);        // 782 (dual)
    const int gAg = (NN * 32 + TB - 1) / TB;       // warp per node

    // CSR by dst (rebuilt every call: deterministic work)
    k_init<<<gN, TB>>>();
    k_hist<<<gE, TB>>>(ei);
    k_scan_block<<<gSc, 1024>>>();
    k_scan_top<<<1, 64>>>(gSc);
    k_finalize_csr<<<gN, TB>>>();
    k_scatter<<<gE, TB>>>(ei);

    // layer 1 (K=768): A = external x
    k_mma_dual<<<gGm, TB>>>(x, -1, Wl[0], Wr[0], NN, FIN);
    k_aggregate<<<gAg, TB>>>(att[0], bia[0], 2, 1);
    // layer 2: A = hA(2)
    k_mma_dual<<<gGm, TB>>>(nullptr, 2, Wl[1], Wr[1], NN, HD);
    k_aggregate<<<gAg, TB>>>(att[1], bia[1], 3, 1);
    // layer 3: A = hB(3)
    k_mma_dual<<<gGm, TB>>>(nullptr, 3, Wl[2], Wr[2], NN, HD);
    k_aggregate<<<gAg, TB>>>(att[2], bia[2], 2, 1);
    // layer 4 (no relu): A = hA(2)
    k_mma_dual<<<gGm, TB>>>(nullptr, 2, Wl[3], Wr[3], NN, HD);
    k_aggregate<<<gAg, TB>>>(att[3], bia[3], 3, 0);

    // mean-pool + classifier
    k_pool<<<512, 128>>>(3);
    k_classify<<<1, 32>>>(clfW, clfb, out);
}